// round 16
// baseline (speedup 1.0000x reference)
#include <cuda_runtime.h>
#include <cuda_bf16.h>

// ===========================================================================
// StaticMHCAdapter: out[b,t] = sum_s (h_res[s,t] + h_post[t]*h_pre[s]) * x[b,s]
// h_res = sinkhorn_log(H_res_logits); h_pre/h_post = softmax.
// x = residuals [B=4, S=4, T, D]. 4x4 stream mix -> pure HBM streaming.
// R16 (= R13 fused design, unexecuted: broker timeouts R13-R15): SINGLE fused
// kernel. Each block computes the tiny Sinkhorn/softmax redundantly in warp 0
// (memory-bound kernel -> prelude ALU overlaps other blocks' memory),
// eliminating the prep launch + inter-kernel dependency (12.3us tail in R12).
// Mix: VPT=2, 8 front-batched LDG.128, __ldcs/__stcs.
// ===========================================================================

#define NS 4
#define SINKHORN_ITERS 10
#define SINKHORN_TAU 0.05f
#define VPT 2                      // float4s per thread per stream
#define TPB 256

// --------------------------------------------------------------------------
// Block-level prelude: warp 0 computes M[t*NS+s] into sM. Caller syncthreads.
// --------------------------------------------------------------------------
__device__ __forceinline__
void compute_M_warp0(const float* __restrict__ hres_logits,
                     const float* __restrict__ hpre_logits,
                     const float* __restrict__ hpost_logits,
                     float* __restrict__ sM,        // [16] smem, t-major
                     float* __restrict__ sw)        // [24] smem scratch
{
    float* z = sw;            // [16] z[i*4+j]
    float* u = sw + 16;       // [4]
    float* v = sw + 20;       // [4]
    const int t = threadIdx.x;

    if (t < 16) z[t] = hres_logits[t] * (1.0f / SINKHORN_TAU);
    if (t < NS) { u[t] = 0.f; v[t] = 0.f; }
    __syncwarp();

    for (int it = 0; it < SINKHORN_ITERS; it++) {
        // u[i] = -logsumexp_j(z[i][j] + v[j])
        if (t < NS) {
            float a0 = z[t * 4 + 0] + v[0], a1 = z[t * 4 + 1] + v[1];
            float a2 = z[t * 4 + 2] + v[2], a3 = z[t * 4 + 3] + v[3];
            float m = fmaxf(fmaxf(a0, a1), fmaxf(a2, a3));
            float s = __expf(a0 - m) + __expf(a1 - m) +
                      __expf(a2 - m) + __expf(a3 - m);
            u[t] = -(m + __logf(s));
        }
        __syncwarp();
        // v[j] = -logsumexp_i(z[i][j] + u[i])
        if (t < NS) {
            float a0 = z[0 * 4 + t] + u[0], a1 = z[1 * 4 + t] + u[1];
            float a2 = z[2 * 4 + t] + u[2], a3 = z[3 * 4 + t] + u[3];
            float m = fmaxf(fmaxf(a0, a1), fmaxf(a2, a3));
            float s = __expf(a0 - m) + __expf(a1 - m) +
                      __expf(a2 - m) + __expf(a3 - m);
            v[t] = -(m + __logf(s));
        }
        __syncwarp();
    }

    // sM[tcol*NS + s] = exp(z[s][tcol]+u[s]+v[tcol]) + hpost[tcol]*hpre[s]
    if (t < 16) {
        const int tcol = t >> 2, s = t & 3;

        // softmax(hpre)[s] (redundant per-thread, registers only)
        float l0 = hpre_logits[0], l1 = hpre_logits[1],
              l2 = hpre_logits[2], l3 = hpre_logits[3];
        float m = fmaxf(fmaxf(l0, l1), fmaxf(l2, l3));
        float e0 = __expf(l0 - m), e1 = __expf(l1 - m),
              e2 = __expf(l2 - m), e3 = __expf(l3 - m);
        float pre_s = ((s == 0) ? e0 : (s == 1) ? e1 : (s == 2) ? e2 : e3)
                      / (e0 + e1 + e2 + e3);

        // softmax(hpost)[tcol]
        float p0 = hpost_logits[0], p1 = hpost_logits[1],
              p2 = hpost_logits[2], p3 = hpost_logits[3];
        float mp = fmaxf(fmaxf(p0, p1), fmaxf(p2, p3));
        float f0 = __expf(p0 - mp), f1 = __expf(p1 - mp),
              f2 = __expf(p2 - mp), f3 = __expf(p3 - mp);
        float post_t = ((tcol == 0) ? f0 : (tcol == 1) ? f1 :
                        (tcol == 2) ? f2 : f3) / (f0 + f1 + f2 + f3);

        sM[t] = __expf(z[s * 4 + tcol] + u[s] + v[tcol]) + post_t * pre_s;
    }
}

// --------------------------------------------------------------------------
// Fused kernel. GUARDED=false assumes every idx in range (exact shapes).
// --------------------------------------------------------------------------
template <bool GUARDED>
__device__ __forceinline__
void fused_body(const float4* __restrict__ x, float4* __restrict__ out,
                const float* __restrict__ hres_logits,
                const float* __restrict__ hpre_logits,
                const float* __restrict__ hpost_logits, int td4) {
    __shared__ float sM[16];
    __shared__ float sw[24];

    if (threadIdx.x < 32)
        compute_M_warp0(hres_logits, hpre_logits, hpost_logits, sM, sw);
    __syncthreads();

    const int base_idx = blockIdx.x * (TPB * VPT) + threadIdx.x;
    const int b = blockIdx.y;
    const size_t plane = (size_t)td4;

    // Coefficient rows from smem (broadcast LDS.128)
    const float4* Mv = reinterpret_cast<const float4*>(sM);
    float4 mt[NS];
    #pragma unroll
    for (int t = 0; t < NS; t++) mt[t] = Mv[t];

    const float4* bx = x   + (size_t)b * NS * plane;
    float4*       bo = out + (size_t)b * NS * plane;

    // 8 independent, front-batched streaming loads
    float4 v[NS][VPT];
    #pragma unroll
    for (int s = 0; s < NS; s++)
        #pragma unroll
        for (int k = 0; k < VPT; k++) {
            const int idx = base_idx + k * TPB;
            if (!GUARDED || idx < td4) v[s][k] = __ldcs(bx + s * plane + idx);
        }

    #pragma unroll
    for (int t = 0; t < NS; t++) {
        const float c0 = mt[t].x, c1 = mt[t].y, c2 = mt[t].z, c3 = mt[t].w;
        #pragma unroll
        for (int k = 0; k < VPT; k++) {
            const int idx = base_idx + k * TPB;
            if (!GUARDED || idx < td4) {
                float4 r;
                r.x = c0 * v[0][k].x + c1 * v[1][k].x + c2 * v[2][k].x + c3 * v[3][k].x;
                r.y = c0 * v[0][k].y + c1 * v[1][k].y + c2 * v[2][k].y + c3 * v[3][k].y;
                r.z = c0 * v[0][k].z + c1 * v[1][k].z + c2 * v[2][k].z + c3 * v[3][k].z;
                r.w = c0 * v[0][k].w + c1 * v[1][k].w + c2 * v[2][k].w + c3 * v[3][k].w;
                __stcs(bo + t * plane + idx, r);
            }
        }
    }
}

__global__ __launch_bounds__(TPB)
void fused_kernel_exact(const float4* __restrict__ x, float4* __restrict__ out,
                        const float* __restrict__ hres_logits,
                        const float* __restrict__ hpre_logits,
                        const float* __restrict__ hpost_logits, int td4) {
    fused_body<false>(x, out, hres_logits, hpre_logits, hpost_logits, td4);
}

__global__ __launch_bounds__(TPB)
void fused_kernel_guarded(const float4* __restrict__ x, float4* __restrict__ out,
                          const float* __restrict__ hres_logits,
                          const float* __restrict__ hpre_logits,
                          const float* __restrict__ hpost_logits, int td4) {
    fused_body<true>(x, out, hres_logits, hpre_logits, hpost_logits, td4);
}

extern "C" void kernel_launch(void* const* d_in, const int* in_sizes, int n_in,
                              void* d_out, int out_size) {
    const float* residuals    = (const float*)d_in[0];   // [B*S, T, D]
    const float* hres_logits  = (const float*)d_in[1];   // [S, S]
    const float* hpre_logits  = (const float*)d_in[2];   // [S]
    const float* hpost_logits = (const float*)d_in[3];   // [S]
    float* out = (float*)d_out;

    const int total  = in_sizes[0];          // B*S*T*D
    const int bs     = 16;                   // leading dim (B*S)
    const int nb     = bs / NS;              // B = 4
    const int plane  = total / bs;           // T*D
    const int td4    = plane / 4;            // float4s per plane
    const int chunk  = TPB * VPT;
    const int blocks = (td4 + chunk - 1) / chunk;

    dim3 grid(blocks, nb, 1);
    if (td4 % chunk == 0) {
        fused_kernel_exact<<<grid, TPB>>>(
            reinterpret_cast<const float4*>(residuals),
            reinterpret_cast<float4*>(out),
            hres_logits, hpre_logits, hpost_logits, td4);
    } else {
        fused_kernel_guarded<<<grid, TPB>>>(
            reinterpret_cast<const float4*>(residuals),
            reinterpret_cast<float4*>(out),
            hres_logits, hpre_logits, hpost_logits, td4);
    }
}